// round 12
// baseline (speedup 1.0000x reference)
#include <cuda_runtime.h>
#include <math.h>

// Problem constants
#define T_TOK 8192
#define DDIM  4096
#define NEXP  64
#define TOPK  8

// GEMM tiling
#define BM    128
#define BK    16
#define NTH   256
#define KHALF (DDIM / 2)       // 2048 (split-K = 2, contiguous halves)
#define NITER (KHALF / BK)     // 128
#define WDUP  128              // duplicated-W row: 64 experts x 2

// Packed fp32x2 FMA: two independent IEEE-rn fp32 FMAs (bit-exact vs 2x fmaf)
#define FMA2(c, a, b) \
    asm("fma.rn.f32x2 %0, %1, %2, %0;" : "+l"(c) : "l"(a), "l"(b))

__device__ __forceinline__ float lo_f(unsigned long long u) {
    return __uint_as_float((unsigned)u);
}
__device__ __forceinline__ float hi_f(unsigned long long u) {
    return __uint_as_float((unsigned)(u >> 32));
}

// Scratch: partial logits [2][T_TOK][NEXP] (4 MB)
__device__ float g_part[2][T_TOK][NEXP];

// ----------------------------------------------------------------------------
// Kernel 1: split-K=2 fp32 GEMM. blockIdx.y = K-half. Each logit half is ONE
// serial ascending fmaf chain (packed f32x2 lanes are independent tokens).
// Block: 128 tokens x 64 experts, 256 threads, 8 tok x 4 exp per thread
// (16 FMA2 per k-step -> 32 cyc of fma work to hide each 4-LDS burst).
// W duplicated in smem so packed b-operands come from broadcast LDS.128.
// grid = 64 x 2 = 128 CTAs = ONE wave on 148 SMs.
// ----------------------------------------------------------------------------
__global__ __launch_bounds__(NTH)
void router_gemm(const float* __restrict__ x, const float* __restrict__ w)
{
    __shared__ __align__(16) float Xs[2][BK][BM];     // [buf][k][token]   16 KB
    __shared__ __align__(16) float Ws2[2][BK][WDUP];  // [buf][k][dup exp] 16 KB

    const int tid = threadIdx.x;
    const int t0  = blockIdx.x * BM;
    const int k0  = blockIdx.y * KHALF;

    const int tt = tid & 15;         // token octet -> tokens tt*8 .. tt*8+7
    const int te = tid >> 4;         // expert quad -> experts te*4 .. te*4+3

    unsigned long long acc[4][4] = {};   // [token pair][expert]

    // staging assignments
    const int xrow = tid >> 1;            // token row (0..127)
    const int xck  = (tid & 1) * 8;       // k offset within BK (0 or 8)
    const int wrow = tid >> 4;            // k row (0..15)
    const int wck  = (tid & 15) * 4;      // expert col (0,4,..,60)

    const float* xg = x + (size_t)(t0 + xrow) * DDIM + k0 + xck;
    const float* wg = w + (size_t)(k0 + wrow) * NEXP + wck;

    // ---- prime: tile 0 -> buf 0 ----
    {
        float4 A0 = *(const float4*)(xg + 0);
        float4 A1 = *(const float4*)(xg + 4);
        float4 W  = *(const float4*)wg;
        Xs[0][xck + 0][xrow] = A0.x;  Xs[0][xck + 1][xrow] = A0.y;
        Xs[0][xck + 2][xrow] = A0.z;  Xs[0][xck + 3][xrow] = A0.w;
        Xs[0][xck + 4][xrow] = A1.x;  Xs[0][xck + 5][xrow] = A1.y;
        Xs[0][xck + 6][xrow] = A1.z;  Xs[0][xck + 7][xrow] = A1.w;
        float* d = &Ws2[0][wrow][wck * 2];
        *(float4*)(d + 0) = make_float4(W.x, W.x, W.y, W.y);
        *(float4*)(d + 4) = make_float4(W.z, W.z, W.w, W.w);
    }
    __syncthreads();

    for (int it = 0; it < NITER; ++it) {
        const int buf = it & 1;
        const bool pf = (it + 1 < NITER);

        float4 A0, A1, W;
        if (pf) {
            const float* xp = xg + (it + 1) * BK;
            A0 = *(const float4*)(xp + 0);
            A1 = *(const float4*)(xp + 4);
            W  = *(const float4*)(wg + (size_t)(it + 1) * BK * NEXP);
        }

        const float* xsb = &Xs[buf][0][tt * 8];
        const float* wsb = &Ws2[buf][0][te * 8];

#pragma unroll
        for (int kk = 0; kk < BK; ++kk) {
            ulonglong2 a0 = *(const ulonglong2*)(xsb + kk * BM);       // tok pairs 0,1
            ulonglong2 a1 = *(const ulonglong2*)(xsb + kk * BM + 4);   // tok pairs 2,3
            ulonglong2 b0 = *(const ulonglong2*)(wsb + kk * WDUP);     // dup exp 0,1
            ulonglong2 b1 = *(const ulonglong2*)(wsb + kk * WDUP + 4); // dup exp 2,3
            FMA2(acc[0][0], a0.x, b0.x); FMA2(acc[0][1], a0.x, b0.y);
            FMA2(acc[0][2], a0.x, b1.x); FMA2(acc[0][3], a0.x, b1.y);
            FMA2(acc[1][0], a0.y, b0.x); FMA2(acc[1][1], a0.y, b0.y);
            FMA2(acc[1][2], a0.y, b1.x); FMA2(acc[1][3], a0.y, b1.y);
            FMA2(acc[2][0], a1.x, b0.x); FMA2(acc[2][1], a1.x, b0.y);
            FMA2(acc[2][2], a1.x, b1.x); FMA2(acc[2][3], a1.x, b1.y);
            FMA2(acc[3][0], a1.y, b0.x); FMA2(acc[3][1], a1.y, b0.y);
            FMA2(acc[3][2], a1.y, b1.x); FMA2(acc[3][3], a1.y, b1.y);
        }

        if (pf) {
            const int nb = buf ^ 1;
            Xs[nb][xck + 0][xrow] = A0.x;  Xs[nb][xck + 1][xrow] = A0.y;
            Xs[nb][xck + 2][xrow] = A0.z;  Xs[nb][xck + 3][xrow] = A0.w;
            Xs[nb][xck + 4][xrow] = A1.x;  Xs[nb][xck + 5][xrow] = A1.y;
            Xs[nb][xck + 6][xrow] = A1.z;  Xs[nb][xck + 7][xrow] = A1.w;
            float* d = &Ws2[nb][wrow][wck * 2];
            *(float4*)(d + 0) = make_float4(W.x, W.x, W.y, W.y);
            *(float4*)(d + 4) = make_float4(W.z, W.z, W.w, W.w);
        }
        __syncthreads();
    }

    // write partials for this K-half (8 tokens x 4 experts per thread)
    float* op = &g_part[blockIdx.y][t0][0];
#pragma unroll
    for (int p = 0; p < 4; ++p) {
        const int r0 = tt * 8 + 2 * p;
        *(float4*)(op + (size_t)r0 * NEXP + te * 4) =
            make_float4(lo_f(acc[p][0]), lo_f(acc[p][1]),
                        lo_f(acc[p][2]), lo_f(acc[p][3]));
        *(float4*)(op + (size_t)(r0 + 1) * NEXP + te * 4) =
            make_float4(hi_f(acc[p][0]), hi_f(acc[p][1]),
                        hi_f(acc[p][2]), hi_f(acc[p][3]));
    }
}

// ----------------------------------------------------------------------------
// Kernel 2: one warp per token. logit = half0 + half1 (ascending slice order,
// scalar rn add -> identical rounding to the R4 passing kernel), then top-8
// (tie: lowest index, matching jax.lax.top_k) + softmax.
// ----------------------------------------------------------------------------
__global__ __launch_bounds__(256)
void router_topk(float* __restrict__ out, int half)
{
    const int warp = (int)((blockIdx.x * blockDim.x + threadIdx.x) >> 5);
    const int lane = threadIdx.x & 31;
    if (warp >= T_TOK) return;

    float v0 = g_part[0][warp][lane]      + g_part[1][warp][lane];
    float v1 = g_part[0][warp][lane + 32] + g_part[1][warp][lane + 32];

    float topv[TOPK];
    int   topi[TOPK];
#pragma unroll
    for (int j = 0; j < TOPK; j++) {
        float bv; int bi;
        if (v0 >= v1) { bv = v0; bi = lane; }
        else          { bv = v1; bi = lane + 32; }
#pragma unroll
        for (int off = 16; off; off >>= 1) {
            float ov = __shfl_xor_sync(0xffffffffu, bv, off);
            int   oi = __shfl_xor_sync(0xffffffffu, bi, off);
            if (ov > bv || (ov == bv && oi < bi)) { bv = ov; bi = oi; }
        }
        topv[j] = bv;
        topi[j] = bi;
        if (bi == lane)           v0 = -INFINITY;
        else if (bi == lane + 32) v1 = -INFINITY;
    }

    const float mx = topv[0];
    float e[TOPK];
    float sum = 0.0f;
#pragma unroll
    for (int j = 0; j < TOPK; j++) { e[j] = expf(topv[j] - mx); sum += e[j]; }
    const float inv = 1.0f / sum;

    if (lane < TOPK) {
        const size_t g = (size_t)warp * TOPK + lane;
        out[g]        = e[lane] * inv;
        out[half + g] = (float)topi[lane];
    }
}

// ----------------------------------------------------------------------------
extern "C" void kernel_launch(void* const* d_in, const int* in_sizes, int n_in,
                              void* d_out, int out_size)
{
    const float* x = (const float*)d_in[0];
    const float* w = (const float*)d_in[1];
    float* out = (float*)d_out;
    const int half = out_size >> 1;

    dim3 grid1(T_TOK / BM, 2);
    router_gemm<<<grid1, NTH>>>(x, w);

    router_topk<<<T_TOK / 8, 256>>>(out, half);
}

// round 13
// speedup vs baseline: 1.4371x; 1.4371x over previous
#include <cuda_runtime.h>
#include <math.h>

// Problem constants
#define T_TOK 8192
#define DDIM  4096
#define NEXP  64
#define TOPK  8

// GEMM tiling
#define BM    64
#define BK    16
#define NTH   256
#define KHALF (DDIM / 2)       // 2048 (split-K = 2, contiguous halves)
#define NITER (KHALF / BK)     // 128

// Packed fp32x2 FMA: two independent IEEE-rn fp32 FMAs (bit-exact vs 2x fmaf)
#define FMA2(c, a, b) \
    asm("fma.rn.f32x2 %0, %1, %2, %0;" : "+l"(c) : "l"(a), "l"(b))

__device__ __forceinline__ float lo_f(unsigned long long u) {
    return __uint_as_float((unsigned)u);
}
__device__ __forceinline__ float hi_f(unsigned long long u) {
    return __uint_as_float((unsigned)(u >> 32));
}
// duplicate a scalar into both f32x2 lanes
__device__ __forceinline__ unsigned long long dup2(float f) {
    unsigned u = __float_as_uint(f);
    return ((unsigned long long)u << 32) | (unsigned long long)u;
}

// Scratch: partial logits [2][T_TOK][NEXP] (4 MB)
__device__ float g_part[2][T_TOK][NEXP];

// ----------------------------------------------------------------------------
// Kernel 1: split-K=2 fp32 GEMM. blockIdx.y = K-half. Each logit half is ONE
// serial ascending fmaf chain; FMA2 lanes = EXPERT PAIRS (packed natively from
// the Ws tile — zero MOVs, broadcast loads since te == warp id). Tokens are
// scalar, duplicated with 2 dup2 per k-step.
// Block: 64 tokens x 64 experts, 256 threads, 2 tok x 8 exp per thread.
// 16 KB smem + <=64 regs -> 4 CTAs/SM (32 warps) ; grid 256 = one wave.
// ----------------------------------------------------------------------------
__global__ __launch_bounds__(NTH, 4)
void router_gemm(const float* __restrict__ x, const float* __restrict__ w)
{
    __shared__ __align__(16) float Xs[2][BK][BM];    // [buf][k][token]  8 KB
    __shared__ __align__(16) float Ws[2][BK][NEXP];  // [buf][k][expert] 8 KB

    const int tid = threadIdx.x;
    const int t0  = blockIdx.x * BM;
    const int k0  = blockIdx.y * KHALF;

    const int tt = tid & 31;         // token pair group -> tokens 2tt, 2tt+1
    const int te = tid >> 5;         // expert octet (== warp id) -> 8te..8te+7

    unsigned long long acc[2][4] = {};   // [token][expert pair]

    // staging assignments (one float4 each for X and W per thread)
    const int xrow = tid >> 2;            // token row (0..63)
    const int xck  = (tid & 3) * 4;       // k offset within BK (0,4,8,12)
    const int wrow = tid >> 4;            // k row (0..15)
    const int wck  = (tid & 15) * 4;      // expert col (0,4,..,60)

    const float* xg = x + (size_t)(t0 + xrow) * DDIM + k0 + xck;
    const float* wg = w + (size_t)(k0 + wrow) * NEXP + wck;

    // ---- prime: tile 0 -> buf 0 ----
    {
        float4 A = *(const float4*)xg;
        float4 W = *(const float4*)wg;
        Xs[0][xck + 0][xrow] = A.x;
        Xs[0][xck + 1][xrow] = A.y;
        Xs[0][xck + 2][xrow] = A.z;
        Xs[0][xck + 3][xrow] = A.w;
        *(float4*)&Ws[0][wrow][wck] = W;
    }
    __syncthreads();

    for (int it = 0; it < NITER; ++it) {
        const int buf = it & 1;
        const bool pf = (it + 1 < NITER);

        float4 A, W;
        if (pf) {
            A = *(const float4*)(xg + (it + 1) * BK);
            W = *(const float4*)(wg + (size_t)(it + 1) * BK * NEXP);
        }

        const float* xsb = &Xs[buf][0][tt * 2];
        const float* wsb = &Ws[buf][0][te * 8];

#pragma unroll
        for (int kk = 0; kk < BK; ++kk) {
            float2     af = *(const float2*)(xsb + kk * BM);           // 2 tokens
            ulonglong2 b01 = *(const ulonglong2*)(wsb + kk * NEXP);     // exp pairs 0,1
            ulonglong2 b23 = *(const ulonglong2*)(wsb + kk * NEXP + 4); // exp pairs 2,3
            unsigned long long a0 = dup2(af.x);
            unsigned long long a1 = dup2(af.y);
            FMA2(acc[0][0], a0, b01.x); FMA2(acc[0][1], a0, b01.y);
            FMA2(acc[0][2], a0, b23.x); FMA2(acc[0][3], a0, b23.y);
            FMA2(acc[1][0], a1, b01.x); FMA2(acc[1][1], a1, b01.y);
            FMA2(acc[1][2], a1, b23.x); FMA2(acc[1][3], a1, b23.y);
        }

        if (pf) {
            const int nb = buf ^ 1;
            Xs[nb][xck + 0][xrow] = A.x;
            Xs[nb][xck + 1][xrow] = A.y;
            Xs[nb][xck + 2][xrow] = A.z;
            Xs[nb][xck + 3][xrow] = A.w;
            *(float4*)&Ws[nb][wrow][wck] = W;
        }
        __syncthreads();
    }

    // write partials for this K-half: 2 tokens x 8 contiguous experts
    float* op = &g_part[blockIdx.y][t0][0];
#pragma unroll
    for (int t = 0; t < 2; ++t) {
        float* r = op + (size_t)(tt * 2 + t) * NEXP + te * 8;
        *(float4*)(r + 0) = make_float4(lo_f(acc[t][0]), hi_f(acc[t][0]),
                                        lo_f(acc[t][1]), hi_f(acc[t][1]));
        *(float4*)(r + 4) = make_float4(lo_f(acc[t][2]), hi_f(acc[t][2]),
                                        lo_f(acc[t][3]), hi_f(acc[t][3]));
    }
}

// ----------------------------------------------------------------------------
// Kernel 2: one warp per token. logit = half0 + half1 (ascending slice order,
// scalar rn add -> identical rounding to the R4 passing kernel), then top-8
// (tie: lowest index, matching jax.lax.top_k) + softmax.
// ----------------------------------------------------------------------------
__global__ __launch_bounds__(256)
void router_topk(float* __restrict__ out, int half)
{
    const int warp = (int)((blockIdx.x * blockDim.x + threadIdx.x) >> 5);
    const int lane = threadIdx.x & 31;
    if (warp >= T_TOK) return;

    float v0 = g_part[0][warp][lane]      + g_part[1][warp][lane];
    float v1 = g_part[0][warp][lane + 32] + g_part[1][warp][lane + 32];

    float topv[TOPK];
    int   topi[TOPK];
#pragma unroll
    for (int j = 0; j < TOPK; j++) {
        float bv; int bi;
        if (v0 >= v1) { bv = v0; bi = lane; }
        else          { bv = v1; bi = lane + 32; }
#pragma unroll
        for (int off = 16; off; off >>= 1) {
            float ov = __shfl_xor_sync(0xffffffffu, bv, off);
            int   oi = __shfl_xor_sync(0xffffffffu, bi, off);
            if (ov > bv || (ov == bv && oi < bi)) { bv = ov; bi = oi; }
        }
        topv[j] = bv;
        topi[j] = bi;
        if (bi == lane)           v0 = -INFINITY;
        else if (bi == lane + 32) v1 = -INFINITY;
    }

    const float mx = topv[0];
    float e[TOPK];
    float sum = 0.0f;
#pragma unroll
    for (int j = 0; j < TOPK; j++) { e[j] = expf(topv[j] - mx); sum += e[j]; }
    const float inv = 1.0f / sum;

    if (lane < TOPK) {
        const size_t g = (size_t)warp * TOPK + lane;
        out[g]        = e[lane] * inv;
        out[half + g] = (float)topi[lane];
    }
}

// ----------------------------------------------------------------------------
extern "C" void kernel_launch(void* const* d_in, const int* in_sizes, int n_in,
                              void* d_out, int out_size)
{
    const float* x = (const float*)d_in[0];
    const float* w = (const float*)d_in[1];
    float* out = (float*)d_out;
    const int half = out_size >> 1;

    dim3 grid1(T_TOK / BM, 2);
    router_gemm<<<grid1, NTH>>>(x, w);

    router_topk<<<T_TOK / 8, 256>>>(out, half);
}

// round 16
// speedup vs baseline: 1.7058x; 1.1870x over previous
#include <cuda_runtime.h>
#include <math.h>

// Problem constants
#define T_TOK 8192
#define DDIM  4096
#define NEXP  64
#define TOPK  8

// GEMM tiling
#define BM    64
#define BK    16
#define NTH   128
#define KHALF (DDIM / 2)       // 2048 (split-K = 2, contiguous halves)
#define NITER (KHALF / BK)     // 128

// Packed fp32x2 FMA: two independent IEEE-rn fp32 FMAs (bit-exact vs 2x fmaf)
#define FMA2(c, a, b) \
    asm("fma.rn.f32x2 %0, %1, %2, %0;" : "+l"(c) : "l"(a), "l"(b))

__device__ __forceinline__ float lo_f(unsigned long long u) {
    return __uint_as_float((unsigned)u);
}
__device__ __forceinline__ float hi_f(unsigned long long u) {
    return __uint_as_float((unsigned)(u >> 32));
}
// duplicate a scalar into both f32x2 lanes
__device__ __forceinline__ unsigned long long dup2(float f) {
    unsigned u = __float_as_uint(f);
    return ((unsigned long long)u << 32) | (unsigned long long)u;
}

// order-preserving float<->uint mapping (monotone; larger float => larger uint)
__device__ __forceinline__ unsigned mono(float f) {
    unsigned b = __float_as_uint(f);
    return (b & 0x80000000u) ? ~b : (b | 0x80000000u);
}
__device__ __forceinline__ float unmono(unsigned u) {
    unsigned b = (u & 0x80000000u) ? (u & 0x7FFFFFFFu) : ~u;
    return __uint_as_float(b);
}

// Scratch: partial logits [2][T_TOK][NEXP] (4 MB)
__device__ float g_part[2][T_TOK][NEXP];

// ----------------------------------------------------------------------------
// Kernel 1: split-K=2 fp32 GEMM. blockIdx.y = K-half. Each logit half is ONE
// serial ascending fmaf chain (FMA2 lanes = expert pairs packed natively from
// Ws — zero MOVs on b; tokens scalar, dup2'd).
// Block: 64 tokens x 64 experts, 128 threads, 4 tok x 8 exp per thread
// -> 16 FMA2 per 4 smem wavefronts (2x the arithmetic density of R13).
// 16 KB smem, launch_bounds(128,4) -> 16 warps/SM, all 256 CTAs co-resident.
// ----------------------------------------------------------------------------
__global__ __launch_bounds__(NTH, 4)
void router_gemm(const float* __restrict__ x, const float* __restrict__ w)
{
    __shared__ __align__(16) float Xs[2][BK][BM];    // [buf][k][token]  8 KB
    __shared__ __align__(16) float Ws[2][BK][NEXP];  // [buf][k][expert] 8 KB

    const int tid = threadIdx.x;
    const int t0  = blockIdx.x * BM;
    const int k0  = blockIdx.y * KHALF;

    const int tt = tid & 15;         // token quad  -> tokens tt*4 .. tt*4+3
    const int te = tid >> 4;         // expert octet -> experts te*8 .. te*8+7

    unsigned long long acc[4][4] = {};   // [token][expert pair]

    // staging: 128 threads, 8 floats each for X (2 float4) and W (2 float4)
    const int xrow = tid >> 1;            // token row (0..63)
    const int xck  = (tid & 1) * 8;       // k offset within BK (0 or 8)
    const int wrow = tid >> 3;            // k row (0..15)
    const int wck  = (tid & 7) * 8;       // expert col (0,8,..,56)

    const float* xg = x + (size_t)(t0 + xrow) * DDIM + k0 + xck;
    const float* wg = w + (size_t)(k0 + wrow) * NEXP + wck;

    // ---- prime: tile 0 -> buf 0 ----
    {
        float4 A0 = *(const float4*)(xg + 0);
        float4 A1 = *(const float4*)(xg + 4);
        float4 W0 = *(const float4*)(wg + 0);
        float4 W1 = *(const float4*)(wg + 4);
        Xs[0][xck + 0][xrow] = A0.x;  Xs[0][xck + 1][xrow] = A0.y;
        Xs[0][xck + 2][xrow] = A0.z;  Xs[0][xck + 3][xrow] = A0.w;
        Xs[0][xck + 4][xrow] = A1.x;  Xs[0][xck + 5][xrow] = A1.y;
        Xs[0][xck + 6][xrow] = A1.z;  Xs[0][xck + 7][xrow] = A1.w;
        *(float4*)&Ws[0][wrow][wck + 0] = W0;
        *(float4*)&Ws[0][wrow][wck + 4] = W1;
    }
    __syncthreads();

    for (int it = 0; it < NITER; ++it) {
        const int buf = it & 1;
        const bool pf = (it + 1 < NITER);

        float4 A0, A1, W0, W1;
        if (pf) {
            const float* xp = xg + (it + 1) * BK;
            A0 = *(const float4*)(xp + 0);
            A1 = *(const float4*)(xp + 4);
            const float* wp = wg + (size_t)(it + 1) * BK * NEXP;
            W0 = *(const float4*)(wp + 0);
            W1 = *(const float4*)(wp + 4);
        }

        const float* xsb = &Xs[buf][0][tt * 4];
        const float* wsb = &Ws[buf][0][te * 8];

#pragma unroll
        for (int kk = 0; kk < BK; ++kk) {
            float4     af  = *(const float4*)(xsb + kk * BM);           // 4 tokens
            ulonglong2 b01 = *(const ulonglong2*)(wsb + kk * NEXP);     // exp pairs 0,1
            ulonglong2 b23 = *(const ulonglong2*)(wsb + kk * NEXP + 4); // exp pairs 2,3
            unsigned long long a0 = dup2(af.x);
            unsigned long long a1 = dup2(af.y);
            unsigned long long a2 = dup2(af.z);
            unsigned long long a3 = dup2(af.w);
            FMA2(acc[0][0], a0, b01.x); FMA2(acc[0][1], a0, b01.y);
            FMA2(acc[0][2], a0, b23.x); FMA2(acc[0][3], a0, b23.y);
            FMA2(acc[1][0], a1, b01.x); FMA2(acc[1][1], a1, b01.y);
            FMA2(acc[1][2], a1, b23.x); FMA2(acc[1][3], a1, b23.y);
            FMA2(acc[2][0], a2, b01.x); FMA2(acc[2][1], a2, b01.y);
            FMA2(acc[2][2], a2, b23.x); FMA2(acc[2][3], a2, b23.y);
            FMA2(acc[3][0], a3, b01.x); FMA2(acc[3][1], a3, b01.y);
            FMA2(acc[3][2], a3, b23.x); FMA2(acc[3][3], a3, b23.y);
        }

        if (pf) {
            const int nb = buf ^ 1;
            Xs[nb][xck + 0][xrow] = A0.x;  Xs[nb][xck + 1][xrow] = A0.y;
            Xs[nb][xck + 2][xrow] = A0.z;  Xs[nb][xck + 3][xrow] = A0.w;
            Xs[nb][xck + 4][xrow] = A1.x;  Xs[nb][xck + 5][xrow] = A1.y;
            Xs[nb][xck + 6][xrow] = A1.z;  Xs[nb][xck + 7][xrow] = A1.w;
            *(float4*)&Ws[nb][wrow][wck + 0] = W0;
            *(float4*)&Ws[nb][wrow][wck + 4] = W1;
        }
        __syncthreads();
    }

    // write partials for this K-half: 4 tokens x 8 contiguous experts
    float* op = &g_part[blockIdx.y][t0][0];
#pragma unroll
    for (int t = 0; t < 4; ++t) {
        float* r = op + (size_t)(tt * 4 + t) * NEXP + te * 8;
        *(float4*)(r + 0) = make_float4(lo_f(acc[t][0]), hi_f(acc[t][0]),
                                        lo_f(acc[t][1]), hi_f(acc[t][1]));
        *(float4*)(r + 4) = make_float4(lo_f(acc[t][2]), hi_f(acc[t][2]),
                                        lo_f(acc[t][3]), hi_f(acc[t][3]));
    }
}

// ----------------------------------------------------------------------------
// Kernel 2: one warp per token. logit = half0 + half1 (ascending slice order,
// scalar rn add -> identical rounding), then top-8 via REDUX max on a
// monotone uint mapping (exact lowest-index tie-break preserved: v0 hits
// (idx<32) take priority over v1 hits, lowest lane within each), + softmax.
// ----------------------------------------------------------------------------
__global__ __launch_bounds__(256)
void router_topk(float* __restrict__ out, int half)
{
    const int warp = (int)((blockIdx.x * blockDim.x + threadIdx.x) >> 5);
    const int lane = threadIdx.x & 31;
    if (warp >= T_TOK) return;

    float v0 = g_part[0][warp][lane]      + g_part[1][warp][lane];
    float v1 = g_part[0][warp][lane + 32] + g_part[1][warp][lane + 32];

    unsigned u0 = mono(v0);
    unsigned u1 = mono(v1);

    float topv[TOPK];
    int   topi[TOPK];
#pragma unroll
    for (int j = 0; j < TOPK; j++) {
        unsigned lm = (u0 > u1) ? u0 : u1;
        unsigned m  = __reduce_max_sync(0xffffffffu, lm);
        unsigned b0 = __ballot_sync(0xffffffffu, u0 == m);
        int bi;
        if (b0) {
            bi = __ffs(b0) - 1;                 // lowest index among v0 hits
        } else {
            unsigned b1 = __ballot_sync(0xffffffffu, u1 == m);
            bi = __ffs(b1) - 1 + 32;
        }
        topv[j] = unmono(m);
        topi[j] = bi;
        if (bi == lane)           u0 = 0u;       // 0 < mono(any finite/-inf)
        else if (bi == lane + 32) u1 = 0u;
    }

    const float mx = topv[0];
    float e[TOPK];
    float sum = 0.0f;
#pragma unroll
    for (int j = 0; j < TOPK; j++) { e[j] = expf(topv[j] - mx); sum += e[j]; }
    const float inv = 1.0f / sum;

    if (lane < TOPK) {
        const size_t g = (size_t)warp * TOPK + lane;
        out[g]        = e[lane] * inv;
        out[half + g] = (float)topi[lane];
    }
}

// ----------------------------------------------------------------------------
extern "C" void kernel_launch(void* const* d_in, const int* in_sizes, int n_in,
                              void* d_out, int out_size)
{
    const float* x = (const float*)d_in[0];
    const float* w = (const float*)d_in[1];
    float* out = (float*)d_out;
    const int half = out_size >> 1;

    dim3 grid1(T_TOK / BM, 2);
    router_gemm<<<grid1, NTH>>>(x, w);

    router_topk<<<T_TOK / 8, 256>>>(out, half);
}